// round 14
// baseline (speedup 1.0000x reference)
#include <cuda_runtime.h>
#include <cuda_fp16.h>
#include <cstdint>
#include <math.h>

#define B_ROWS 4096
#define DIM    256
#define N2     8192
#define NOFFD  2016   // 63*64/2 off-diagonal tiles
#define NTILES 2080
#define NCHUNK 128    // 32 norm-rows per chunk

// Scratch (device globals; allocations forbidden)
__device__ __align__(16) __half g_reps[N2 * DIM];  // normalized reps, fp16 (4 MB)
__device__ float g_pair[N2];        // sim[i,pair(i)]/T (exact fp32)
__device__ float g_denom[N2];       // masked sum of exp(sim/T)
__device__ unsigned g_work;         // norm chunk work-stealing counter
__device__ unsigned g_bdone[32];    // per-128-row-block completed chunk count (0..4)
__device__ unsigned g_ctadone;      // finished-CTA counter (for replay-safe reset)

__device__ __forceinline__ uint32_t smem_u32(const void* p) {
    return (uint32_t)__cvta_generic_to_shared(p);
}
__device__ __forceinline__ __half2 hex2(__half2 x) {
    uint32_t xi = *(uint32_t*)&x, ri;
    asm("ex2.approx.f16x2 %0, %1;" : "=r"(ri) : "r"(xi));
    return *(__half2*)&ri;
}
__device__ __forceinline__ unsigned ld_acq(const unsigned* p) {
    unsigned v;
    asm volatile("ld.acquire.gpu.u32 %0, [%1];" : "=r"(v) : "l"(p));
    return v;
}

// ---------------------------------------------------------------------------
// Fused kernel: work-stolen normalization + fp16 mma.sync GEMM + epilogue.
// 2080 CTAs, 256 threads, 3 CTAs/SM. Off-diag tiles first, diagonals last.
// ---------------------------------------------------------------------------
#define CH_BYTES 18432   // 128 rows * 72 halves * 2B

__global__ void __launch_bounds__(256, 3) sim_kernel(const float* __restrict__ emb_i,
                                                     const float* __restrict__ emb_j,
                                                     const int* __restrict__ tags,
                                                     const int* __restrict__ docs)
{
    extern __shared__ __align__(16) char dsm[];
    uint32_t A_s[2] = { smem_u32(dsm),              smem_u32(dsm) + CH_BYTES };
    uint32_t B_s[2] = { smem_u32(dsm) + 2*CH_BYTES, smem_u32(dsm) + 3*CH_BYTES };
    __half* Agen[2] = { (__half*)dsm,                (__half*)(dsm + CH_BYTES) };
    __half* Bgen[2] = { (__half*)(dsm + 2*CH_BYTES), (__half*)(dsm + 3*CH_BYTES) };

    __shared__ uint32_t rkey[128], ckey[128];
    __shared__ float rowsum[128], colsum[128];
    __shared__ unsigned s_chunk;

    int t    = threadIdx.x;
    int lane = t & 31;
    int wid  = t >> 5;
    int wm   = wid >> 2;   // 0..1
    int wn   = wid & 3;    // 0..3

    // tile mapping: off-diagonal first (bm<bn), diagonals at the end
    int bm, bn;
    if (blockIdx.x < NOFFD) {
        int p = blockIdx.x;
        bm = 0;
        while (p >= 63 - bm) { p -= 63 - bm; bm++; }
        bn = bm + 1 + p;
    } else {
        bm = bn = blockIdx.x - NOFFD;
    }
    int row0 = bm * 128, col0 = bn * 128;
    bool offd = (bm != bn);

    // prologue independent of norm: keys + smem init
    if (t < 128) {
        rowsum[t] = 0.f; colsum[t] = 0.f;
        int gr = (row0 + t) & (B_ROWS - 1);
        int gc = (col0 + t) & (B_ROWS - 1);
        rkey[t] = ((uint32_t)tags[gr] << 16) | (uint32_t)docs[gr];
        ckey[t] = ((uint32_t)tags[gc] << 16) | (uint32_t)docs[gc];
    }

    // ---------------- Phase 1: work-stolen normalization --------------------
    for (;;) {
        if (t == 0) s_chunk = atomicAdd(&g_work, 1u);
        __syncthreads();
        unsigned c = s_chunk;
        if (c >= NCHUNK) break;

        // warp w normalizes rows c*32 + w*4 .. +3
        #pragma unroll 1
        for (int i = 0; i < 4; i++) {
            int row = (int)c * 32 + wid * 4 + i;   // 0..4095
            const float4* ai = (const float4*)emb_i + (size_t)row * 64;
            const float4* bj = (const float4*)emb_j + (size_t)row * 64;
            float4 a0 = ai[lane], a1 = ai[32 + lane];
            float4 b0 = bj[lane], b1 = bj[32 + lane];

            float sa = a0.x*a0.x + a0.y*a0.y + a0.z*a0.z + a0.w*a0.w
                     + a1.x*a1.x + a1.y*a1.y + a1.z*a1.z + a1.w*a1.w;
            float sb = b0.x*b0.x + b0.y*b0.y + b0.z*b0.z + b0.w*b0.w
                     + b1.x*b1.x + b1.y*b1.y + b1.z*b1.z + b1.w*b1.w;
            float sab = a0.x*b0.x + a0.y*b0.y + a0.z*b0.z + a0.w*b0.w
                      + a1.x*b1.x + a1.y*b1.y + a1.z*b1.z + a1.w*b1.w;
            #pragma unroll
            for (int o = 16; o; o >>= 1) {
                sa  += __shfl_xor_sync(0xffffffffu, sa,  o);
                sb  += __shfl_xor_sync(0xffffffffu, sb,  o);
                sab += __shfl_xor_sync(0xffffffffu, sab, o);
            }
            float ri = rsqrtf(sa), rj = rsqrtf(sb);

            __half2 p0 = __float22half2_rn(make_float2(a0.x*ri, a0.y*ri));
            __half2 p1 = __float22half2_rn(make_float2(a0.z*ri, a0.w*ri));
            __half2 p2 = __float22half2_rn(make_float2(a1.x*ri, a1.y*ri));
            __half2 p3 = __float22half2_rn(make_float2(a1.z*ri, a1.w*ri));
            uint2* outA = (uint2*)g_reps + (size_t)row * 64;
            outA[lane]      = make_uint2(*(uint32_t*)&p0, *(uint32_t*)&p1);
            outA[32 + lane] = make_uint2(*(uint32_t*)&p2, *(uint32_t*)&p3);

            __half2 q0 = __float22half2_rn(make_float2(b0.x*rj, b0.y*rj));
            __half2 q1 = __float22half2_rn(make_float2(b0.z*rj, b0.w*rj));
            __half2 q2 = __float22half2_rn(make_float2(b1.x*rj, b1.y*rj));
            __half2 q3 = __float22half2_rn(make_float2(b1.z*rj, b1.w*rj));
            uint2* outB = (uint2*)g_reps + (size_t)(row + B_ROWS) * 64;
            outB[lane]      = make_uint2(*(uint32_t*)&q0, *(uint32_t*)&q1);
            outB[32 + lane] = make_uint2(*(uint32_t*)&q2, *(uint32_t*)&q3);

            if (lane == 0) {
                float pd = sab * ri * rj * 2.0f;   // exact /T (T = 0.5)
                g_pair[row] = pd;
                g_pair[row + B_ROWS] = pd;
            }
        }
        if (t < 32) {   // zero the g_denom slice this chunk owns (both halves)
            g_denom[c * 32 + t] = 0.0f;
            g_denom[B_ROWS + c * 32 + t] = 0.0f;
        }
        __threadfence();     // release all this CTA's stores for this chunk
        __syncthreads();
        if (t == 0) atomicAdd(&g_bdone[c >> 2], 1u);
    }

    // ---------------- Phase 2: wait for the two row-blocks we consume -------
    if (t == 0) {
        while (ld_acq(&g_bdone[bm & 31]) < 4u) { }
        while (ld_acq(&g_bdone[bn & 31]) < 4u) { }
    }
    __syncthreads();

    // ---------------- Phase 3: GEMM (identical to R12 winner) ---------------
    #define FILL_CHUNK(kc, buf)                                                        \
    {                                                                                  \
        int _kc = (kc);                                                                \
        _Pragma("unroll")                                                              \
        for (int i = 0; i < 4; i++) {                                                  \
            int v = t + 256 * i;                                                       \
            int r = v >> 3, c2 = v & 7;                                                \
            uint32_t off = (uint32_t)(r * 144 + c2 * 16);                              \
            const __half* sA = g_reps + (size_t)(row0 + r) * DIM + _kc * 64 + c2 * 8;  \
            const __half* sB = g_reps + (size_t)(col0 + r) * DIM + _kc * 64 + c2 * 8;  \
            asm volatile("cp.async.cg.shared.global [%0], [%1], 16;"                   \
                         :: "r"(A_s[buf] + off), "l"(sA) : "memory");                  \
            asm volatile("cp.async.cg.shared.global [%0], [%1], 16;"                   \
                         :: "r"(B_s[buf] + off), "l"(sB) : "memory");                  \
        }                                                                              \
        asm volatile("cp.async.commit_group;" ::: "memory");                           \
    }

    uint32_t acc[4][4][2];
    #pragma unroll
    for (int a = 0; a < 4; a++)
        #pragma unroll
        for (int b = 0; b < 4; b++) { acc[a][b][0] = 0u; acc[a][b][1] = 0u; }

    int a_row = (lane & 7) + (lane & 8);
    int a_k8  = (lane & 16) ? 8 : 0;
    int b_row = (lane & 7) + ((lane & 16) ? 8 : 0);
    int b_k8  = (lane & 8) ? 8 : 0;

    FILL_CHUNK(0, 0);
    FILL_CHUNK(1, 1);

    #pragma unroll
    for (int kc = 0; kc < 4; kc++) {
        if (kc < 3)
            asm volatile("cp.async.wait_group 1;" ::: "memory");
        else
            asm volatile("cp.async.wait_group 0;" ::: "memory");
        __syncthreads();

        int buf = kc & 1;
        __half* Ab = Agen[buf];
        __half* Bb = Bgen[buf];

        #pragma unroll
        for (int ks = 0; ks < 4; ks++) {
            uint32_t af[4][4];
            #pragma unroll
            for (int mf = 0; mf < 4; mf++) {
                uint32_t addr = smem_u32(Ab + (wm * 64 + mf * 16 + a_row) * 72
                                            + ks * 16 + a_k8);
                asm volatile("ldmatrix.sync.aligned.m8n8.x4.shared.b16 {%0,%1,%2,%3}, [%4];"
                    : "=r"(af[mf][0]), "=r"(af[mf][1]), "=r"(af[mf][2]), "=r"(af[mf][3])
                    : "r"(addr));
            }
            uint32_t bfr[4][2];
            #pragma unroll
            for (int nf2 = 0; nf2 < 2; nf2++) {
                uint32_t addr = smem_u32(Bb + (wn * 32 + nf2 * 16 + b_row) * 72
                                            + ks * 16 + b_k8);
                asm volatile("ldmatrix.sync.aligned.m8n8.x4.shared.b16 {%0,%1,%2,%3}, [%4];"
                    : "=r"(bfr[nf2*2][0]), "=r"(bfr[nf2*2][1]),
                      "=r"(bfr[nf2*2+1][0]), "=r"(bfr[nf2*2+1][1])
                    : "r"(addr));
            }
            #pragma unroll
            for (int mf = 0; mf < 4; mf++)
                #pragma unroll
                for (int nf = 0; nf < 4; nf++)
                    asm volatile(
                        "mma.sync.aligned.m16n8k16.row.col.f16.f16.f16.f16 "
                        "{%0,%1},{%2,%3,%4,%5},{%6,%7},{%0,%1};"
                        : "+r"(acc[mf][nf][0]), "+r"(acc[mf][nf][1])
                        : "r"(af[mf][0]), "r"(af[mf][1]), "r"(af[mf][2]), "r"(af[mf][3]),
                          "r"(bfr[nf][0]), "r"(bfr[nf][1]));
        }

        if (kc < 2) {
            __syncthreads();
            FILL_CHUNK(kc + 2, buf);
        }
    }
    #undef FILL_CHUNK

    // ---------------- Epilogue: f16x2 ex2 + mask + row/col sums -------------
    const __half2 SC = __float2half2_rn(2.885390082f);   // 2*log2(e): exp(2s)=ex2(s*SC)
    float colacc[4][2];
    #pragma unroll
    for (int nf = 0; nf < 4; nf++) { colacc[nf][0] = 0.f; colacc[nf][1] = 0.f; }

    #pragma unroll
    for (int mf = 0; mf < 4; mf++) {
        int r0l = wm * 64 + mf * 16 + (lane >> 2);
        int r1l = r0l + 8;
        uint32_t rk0 = rkey[r0l], rk1 = rkey[r1l];
        float rs0 = 0.f, rs1 = 0.f;
        #pragma unroll
        for (int nf = 0; nf < 4; nf++) {
            int c0l = wn * 32 + nf * 8 + (lane & 3) * 2;
            uint32_t ck0 = ckey[c0l], ck1 = ckey[c0l + 1];
            uint32_t x00 = rk0 ^ ck0, x01 = rk0 ^ ck1;
            uint32_t x10 = rk1 ^ ck0, x11 = rk1 ^ ck1;
            __half2 e0h = hex2(__hmul2(*(__half2*)&acc[mf][nf][0], SC));
            __half2 e1h = hex2(__hmul2(*(__half2*)&acc[mf][nf][1], SC));
            float2 f01 = __half22float2(e0h);
            float2 f23 = __half22float2(e1h);
            float v00 = ((x00 >> 16) && (x00 & 0xffffu)) ? f01.x : 0.f;
            float v01 = ((x01 >> 16) && (x01 & 0xffffu)) ? f01.y : 0.f;
            float v10 = ((x10 >> 16) && (x10 & 0xffffu)) ? f23.x : 0.f;
            float v11 = ((x11 >> 16) && (x11 & 0xffffu)) ? f23.y : 0.f;
            rs0 += v00 + v01;
            rs1 += v10 + v11;
            colacc[nf][0] += v00 + v10;
            colacc[nf][1] += v01 + v11;
        }
        rs0 += __shfl_xor_sync(0xffffffffu, rs0, 1);
        rs0 += __shfl_xor_sync(0xffffffffu, rs0, 2);
        rs1 += __shfl_xor_sync(0xffffffffu, rs1, 1);
        rs1 += __shfl_xor_sync(0xffffffffu, rs1, 2);
        if ((lane & 3) == 0) {
            atomicAdd(&rowsum[r0l], rs0);
            atomicAdd(&rowsum[r1l], rs1);
        }
    }

    if (offd) {
        #pragma unroll
        for (int nf = 0; nf < 4; nf++) {
            float c0 = colacc[nf][0], c1 = colacc[nf][1];
            c0 += __shfl_xor_sync(0xffffffffu, c0, 4);
            c0 += __shfl_xor_sync(0xffffffffu, c0, 8);
            c0 += __shfl_xor_sync(0xffffffffu, c0, 16);
            c1 += __shfl_xor_sync(0xffffffffu, c1, 4);
            c1 += __shfl_xor_sync(0xffffffffu, c1, 8);
            c1 += __shfl_xor_sync(0xffffffffu, c1, 16);
            if (lane < 4) {
                int c = wn * 32 + nf * 8 + lane * 2;
                atomicAdd(&colsum[c], c0);
                atomicAdd(&colsum[c + 1], c1);
            }
        }
    }
    __syncthreads();

    if (t < 128) {
        atomicAdd(&g_denom[row0 + t], rowsum[t]);
        if (offd) atomicAdd(&g_denom[col0 + t], colsum[t]);
    }

    // ---------------- Replay-safe counter reset (last CTA) ------------------
    __threadfence();
    if (t == 0) {
        unsigned d = atomicAdd(&g_ctadone, 1u);
        if (d == NTILES - 1u) {
            g_work = 0u;
            g_ctadone = 0u;
            #pragma unroll
            for (int i = 0; i < 32; i++) g_bdone[i] = 0u;
            __threadfence();
        }
    }
}

// ---------------------------------------------------------------------------
// Kernel 2: loss = mean( log(denom + 0.1) - log(numerator) )
// ---------------------------------------------------------------------------
__global__ void __launch_bounds__(1024) loss_kernel(float* __restrict__ out)
{
    int t = threadIdx.x;
    float s = 0.f;
    #pragma unroll
    for (int r = t; r < N2; r += 1024)
        s += __logf(g_denom[r] + 0.1f) - g_pair[r];

    #pragma unroll
    for (int o = 16; o; o >>= 1) s += __shfl_xor_sync(0xffffffffu, s, o);

    __shared__ float red[32];
    if ((t & 31) == 0) red[t >> 5] = s;
    __syncthreads();
    if (t == 0) {
        float tot = 0.f;
        #pragma unroll
        for (int k = 0; k < 32; k++) tot += red[k];
        out[0] = tot / (float)N2;
    }
}

// ---------------------------------------------------------------------------
#define SIM_DSMEM (4 * CH_BYTES)   // 73728 B; 3 CTAs/SM

extern "C" void kernel_launch(void* const* d_in, const int* in_sizes, int n_in,
                              void* d_out, int out_size)
{
    const float* emb_i = (const float*)d_in[0];
    const float* emb_j = (const float*)d_in[1];
    const int*   tags  = (const int*)d_in[2];
    const int*   docs  = (const int*)d_in[n_in - 1];

    cudaFuncSetAttribute(sim_kernel, cudaFuncAttributeMaxDynamicSharedMemorySize, SIM_DSMEM);

    sim_kernel<<<NTILES, 256, SIM_DSMEM>>>(emb_i, emb_j, tags, docs);
    loss_kernel<<<1, 1024>>>((float*)d_out);
}

// round 15
// speedup vs baseline: 1.1629x; 1.1629x over previous
#include <cuda_runtime.h>
#include <cuda_fp16.h>
#include <cstdint>
#include <math.h>

#define B_ROWS 4096
#define DIM    256
#define N2     8192
#define NOFFD  2016   // 63*64/2 off-diagonal tiles

// Scratch (device globals; allocations forbidden)
__device__ __align__(16) __half g_reps[N2 * DIM];  // normalized reps, fp16 (4 MB)
__device__ float g_pair[N2];    // sim[i,pair(i)]/T (exact fp32)
__device__ float g_denom[N2];   // masked sum of exp(sim/T)

__device__ __forceinline__ uint32_t smem_u32(const void* p) {
    return (uint32_t)__cvta_generic_to_shared(p);
}
__device__ __forceinline__ __half2 hex2(__half2 x) {
    uint32_t xi = *(uint32_t*)&x, ri;
    asm("ex2.approx.f16x2 %0, %1;" : "=r"(ri) : "r"(xi));
    return *(__half2*)&ri;
}

// ---------------------------------------------------------------------------
// Kernel 1: normalization. Warp-per-row; 1024 blocks x 128 threads.
// Also zeroes g_denom and out[0] (for loss atomics).
// ---------------------------------------------------------------------------
__global__ void __launch_bounds__(128) norm_kernel(const float* __restrict__ emb_i,
                                                   const float* __restrict__ emb_j,
                                                   float* __restrict__ out)
{
    int t = threadIdx.x, lane = t & 31, w = t >> 5;
    if (blockIdx.x < 64) g_denom[blockIdx.x * 128 + t] = 0.0f;
    if (blockIdx.x == 0 && t == 0) out[0] = 0.0f;

    int row = blockIdx.x * 4 + w;    // 0..4095
    const float4* ai = (const float4*)emb_i + (size_t)row * 64;
    const float4* bj = (const float4*)emb_j + (size_t)row * 64;
    float4 a0 = ai[lane], a1 = ai[32 + lane];
    float4 b0 = bj[lane], b1 = bj[32 + lane];

    float sa = a0.x*a0.x + a0.y*a0.y + a0.z*a0.z + a0.w*a0.w
             + a1.x*a1.x + a1.y*a1.y + a1.z*a1.z + a1.w*a1.w;
    float sb = b0.x*b0.x + b0.y*b0.y + b0.z*b0.z + b0.w*b0.w
             + b1.x*b1.x + b1.y*b1.y + b1.z*b1.z + b1.w*b1.w;
    float sab = a0.x*b0.x + a0.y*b0.y + a0.z*b0.z + a0.w*b0.w
              + a1.x*b1.x + a1.y*b1.y + a1.z*b1.z + a1.w*b1.w;
    #pragma unroll
    for (int o = 16; o; o >>= 1) {
        sa  += __shfl_xor_sync(0xffffffffu, sa,  o);
        sb  += __shfl_xor_sync(0xffffffffu, sb,  o);
        sab += __shfl_xor_sync(0xffffffffu, sab, o);
    }
    float ri = rsqrtf(sa), rj = rsqrtf(sb);

    __half2 p0 = __float22half2_rn(make_float2(a0.x*ri, a0.y*ri));
    __half2 p1 = __float22half2_rn(make_float2(a0.z*ri, a0.w*ri));
    __half2 p2 = __float22half2_rn(make_float2(a1.x*ri, a1.y*ri));
    __half2 p3 = __float22half2_rn(make_float2(a1.z*ri, a1.w*ri));
    uint2* outA = (uint2*)g_reps + (size_t)row * 64;
    outA[lane]      = make_uint2(*(uint32_t*)&p0, *(uint32_t*)&p1);
    outA[32 + lane] = make_uint2(*(uint32_t*)&p2, *(uint32_t*)&p3);

    __half2 q0 = __float22half2_rn(make_float2(b0.x*rj, b0.y*rj));
    __half2 q1 = __float22half2_rn(make_float2(b0.z*rj, b0.w*rj));
    __half2 q2 = __float22half2_rn(make_float2(b1.x*rj, b1.y*rj));
    __half2 q3 = __float22half2_rn(make_float2(b1.z*rj, b1.w*rj));
    uint2* outB = (uint2*)g_reps + (size_t)(row + B_ROWS) * 64;
    outB[lane]      = make_uint2(*(uint32_t*)&q0, *(uint32_t*)&q1);
    outB[32 + lane] = make_uint2(*(uint32_t*)&q2, *(uint32_t*)&q3);

    if (lane == 0) {
        float pd = sab * ri * rj * 2.0f;   // exact /T (T = 0.5)
        g_pair[row] = pd;
        g_pair[row + B_ROWS] = pd;
    }
}

// ---------------------------------------------------------------------------
// Kernel 2: fp16 mma.sync (fp16 accum), 2-stage cp.async smem pipeline,
// 3 CTAs/SM (24 warps/SM), 64x32 warp tiles, fused exp/mask/row+col sums.
// Off-diag tiles first, cheap diagonal tiles last. (R12 winner, unchanged.)
// ---------------------------------------------------------------------------
#define CH_BYTES 18432   // 128 rows * 72 halves * 2B

__global__ void __launch_bounds__(256, 3) sim_kernel(const int* __restrict__ tags,
                                                     const int* __restrict__ docs)
{
    extern __shared__ __align__(16) char dsm[];
    uint32_t A_s[2] = { smem_u32(dsm),              smem_u32(dsm) + CH_BYTES };
    uint32_t B_s[2] = { smem_u32(dsm) + 2*CH_BYTES, smem_u32(dsm) + 3*CH_BYTES };
    __half* Agen[2] = { (__half*)dsm,                (__half*)(dsm + CH_BYTES) };
    __half* Bgen[2] = { (__half*)(dsm + 2*CH_BYTES), (__half*)(dsm + 3*CH_BYTES) };

    __shared__ uint32_t rkey[128], ckey[128];
    __shared__ float rowsum[128], colsum[128];

    int t    = threadIdx.x;
    int lane = t & 31;
    int wid  = t >> 5;
    int wm   = wid >> 2;   // 0..1
    int wn   = wid & 3;    // 0..3

    // tile mapping: off-diagonal first (bm<bn), diagonals at the end
    int bm, bn;
    if (blockIdx.x < NOFFD) {
        int p = blockIdx.x;
        bm = 0;
        while (p >= 63 - bm) { p -= 63 - bm; bm++; }
        bn = bm + 1 + p;
    } else {
        bm = bn = blockIdx.x - NOFFD;
    }
    int row0 = bm * 128, col0 = bn * 128;
    bool offd = (bm != bn);

    if (t < 128) {
        rowsum[t] = 0.f; colsum[t] = 0.f;
        int gr = (row0 + t) & (B_ROWS - 1);
        int gc = (col0 + t) & (B_ROWS - 1);
        rkey[t] = ((uint32_t)tags[gr] << 16) | (uint32_t)docs[gr];
        ckey[t] = ((uint32_t)tags[gc] << 16) | (uint32_t)docs[gc];
    }

    #define FILL_CHUNK(kc, buf)                                                        \
    {                                                                                  \
        int _kc = (kc);                                                                \
        _Pragma("unroll")                                                              \
        for (int i = 0; i < 4; i++) {                                                  \
            int v = t + 256 * i;                                                       \
            int r = v >> 3, c = v & 7;                                                 \
            uint32_t off = (uint32_t)(r * 144 + c * 16);                               \
            const __half* sA = g_reps + (size_t)(row0 + r) * DIM + _kc * 64 + c * 8;   \
            const __half* sB = g_reps + (size_t)(col0 + r) * DIM + _kc * 64 + c * 8;   \
            asm volatile("cp.async.cg.shared.global [%0], [%1], 16;"                   \
                         :: "r"(A_s[buf] + off), "l"(sA) : "memory");                  \
            asm volatile("cp.async.cg.shared.global [%0], [%1], 16;"                   \
                         :: "r"(B_s[buf] + off), "l"(sB) : "memory");                  \
        }                                                                              \
        asm volatile("cp.async.commit_group;" ::: "memory");                           \
    }

    uint32_t acc[4][4][2];
    #pragma unroll
    for (int a = 0; a < 4; a++)
        #pragma unroll
        for (int b = 0; b < 4; b++) { acc[a][b][0] = 0u; acc[a][b][1] = 0u; }

    int a_row = (lane & 7) + (lane & 8);
    int a_k8  = (lane & 16) ? 8 : 0;
    int b_row = (lane & 7) + ((lane & 16) ? 8 : 0);
    int b_k8  = (lane & 8) ? 8 : 0;

    FILL_CHUNK(0, 0);
    FILL_CHUNK(1, 1);

    #pragma unroll
    for (int kc = 0; kc < 4; kc++) {
        if (kc < 3)
            asm volatile("cp.async.wait_group 1;" ::: "memory");
        else
            asm volatile("cp.async.wait_group 0;" ::: "memory");
        __syncthreads();

        int buf = kc & 1;
        __half* Ab = Agen[buf];
        __half* Bb = Bgen[buf];

        #pragma unroll
        for (int ks = 0; ks < 4; ks++) {
            uint32_t af[4][4];
            #pragma unroll
            for (int mf = 0; mf < 4; mf++) {
                uint32_t addr = smem_u32(Ab + (wm * 64 + mf * 16 + a_row) * 72
                                            + ks * 16 + a_k8);
                asm volatile("ldmatrix.sync.aligned.m8n8.x4.shared.b16 {%0,%1,%2,%3}, [%4];"
                    : "=r"(af[mf][0]), "=r"(af[mf][1]), "=r"(af[mf][2]), "=r"(af[mf][3])
                    : "r"(addr));
            }
            uint32_t bfr[4][2];
            #pragma unroll
            for (int nf2 = 0; nf2 < 2; nf2++) {
                uint32_t addr = smem_u32(Bb + (wn * 32 + nf2 * 16 + b_row) * 72
                                            + ks * 16 + b_k8);
                asm volatile("ldmatrix.sync.aligned.m8n8.x4.shared.b16 {%0,%1,%2,%3}, [%4];"
                    : "=r"(bfr[nf2*2][0]), "=r"(bfr[nf2*2][1]),
                      "=r"(bfr[nf2*2+1][0]), "=r"(bfr[nf2*2+1][1])
                    : "r"(addr));
            }
            #pragma unroll
            for (int mf = 0; mf < 4; mf++)
                #pragma unroll
                for (int nf = 0; nf < 4; nf++)
                    asm volatile(
                        "mma.sync.aligned.m16n8k16.row.col.f16.f16.f16.f16 "
                        "{%0,%1},{%2,%3,%4,%5},{%6,%7},{%0,%1};"
                        : "+r"(acc[mf][nf][0]), "+r"(acc[mf][nf][1])
                        : "r"(af[mf][0]), "r"(af[mf][1]), "r"(af[mf][2]), "r"(af[mf][3]),
                          "r"(bfr[nf][0]), "r"(bfr[nf][1]));
        }

        if (kc < 2) {
            __syncthreads();
            FILL_CHUNK(kc + 2, buf);
        }
    }
    #undef FILL_CHUNK

    // ---------------- Epilogue: f16x2 ex2 + mask + row/col sums -------------
    const __half2 SC = __float2half2_rn(2.885390082f);   // 2*log2(e): exp(2s)=ex2(s*SC)
    float colacc[4][2];
    #pragma unroll
    for (int nf = 0; nf < 4; nf++) { colacc[nf][0] = 0.f; colacc[nf][1] = 0.f; }

    #pragma unroll
    for (int mf = 0; mf < 4; mf++) {
        int r0l = wm * 64 + mf * 16 + (lane >> 2);
        int r1l = r0l + 8;
        uint32_t rk0 = rkey[r0l], rk1 = rkey[r1l];
        float rs0 = 0.f, rs1 = 0.f;
        #pragma unroll
        for (int nf = 0; nf < 4; nf++) {
            int c0l = wn * 32 + nf * 8 + (lane & 3) * 2;
            uint32_t ck0 = ckey[c0l], ck1 = ckey[c0l + 1];
            uint32_t x00 = rk0 ^ ck0, x01 = rk0 ^ ck1;
            uint32_t x10 = rk1 ^ ck0, x11 = rk1 ^ ck1;
            __half2 e0h = hex2(__hmul2(*(__half2*)&acc[mf][nf][0], SC));
            __half2 e1h = hex2(__hmul2(*(__half2*)&acc[mf][nf][1], SC));
            float2 f01 = __half22float2(e0h);
            float2 f23 = __half22float2(e1h);
            float v00 = ((x00 >> 16) && (x00 & 0xffffu)) ? f01.x : 0.f;
            float v01 = ((x01 >> 16) && (x01 & 0xffffu)) ? f01.y : 0.f;
            float v10 = ((x10 >> 16) && (x10 & 0xffffu)) ? f23.x : 0.f;
            float v11 = ((x11 >> 16) && (x11 & 0xffffu)) ? f23.y : 0.f;
            rs0 += v00 + v01;
            rs1 += v10 + v11;
            colacc[nf][0] += v00 + v10;
            colacc[nf][1] += v01 + v11;
        }
        rs0 += __shfl_xor_sync(0xffffffffu, rs0, 1);
        rs0 += __shfl_xor_sync(0xffffffffu, rs0, 2);
        rs1 += __shfl_xor_sync(0xffffffffu, rs1, 1);
        rs1 += __shfl_xor_sync(0xffffffffu, rs1, 2);
        if ((lane & 3) == 0) {
            atomicAdd(&rowsum[r0l], rs0);
            atomicAdd(&rowsum[r1l], rs1);
        }
    }

    if (offd) {
        #pragma unroll
        for (int nf = 0; nf < 4; nf++) {
            float c0 = colacc[nf][0], c1 = colacc[nf][1];
            c0 += __shfl_xor_sync(0xffffffffu, c0, 4);
            c0 += __shfl_xor_sync(0xffffffffu, c0, 8);
            c0 += __shfl_xor_sync(0xffffffffu, c0, 16);
            c1 += __shfl_xor_sync(0xffffffffu, c1, 4);
            c1 += __shfl_xor_sync(0xffffffffu, c1, 8);
            c1 += __shfl_xor_sync(0xffffffffu, c1, 16);
            if (lane < 4) {
                int c = wn * 32 + nf * 8 + lane * 2;
                atomicAdd(&colsum[c], c0);
                atomicAdd(&colsum[c + 1], c1);
            }
        }
    }
    __syncthreads();

    if (t < 128) {
        atomicAdd(&g_denom[row0 + t], rowsum[t]);
        if (offd) atomicAdd(&g_denom[col0 + t], colsum[t]);
    }
}

// ---------------------------------------------------------------------------
// Kernel 3: parallel loss. 16 blocks x 512 threads, one row per thread,
// block partial sums -> atomicAdd into out[0] (zeroed by norm_kernel).
// ---------------------------------------------------------------------------
__global__ void __launch_bounds__(512) loss_kernel(float* __restrict__ out)
{
    int t = threadIdx.x;
    int r = blockIdx.x * 512 + t;    // 0..8191
    float s = __logf(g_denom[r] + 0.1f) - g_pair[r];

    #pragma unroll
    for (int o = 16; o; o >>= 1) s += __shfl_xor_sync(0xffffffffu, s, o);

    __shared__ float red[16];
    if ((t & 31) == 0) red[t >> 5] = s;
    __syncthreads();
    if (t == 0) {
        float tot = 0.f;
        #pragma unroll
        for (int k = 0; k < 16; k++) tot += red[k];
        atomicAdd(out, tot / (float)N2);
    }
}

// ---------------------------------------------------------------------------
#define SIM_DSMEM (4 * CH_BYTES)   // 73728 B; 3 CTAs/SM

extern "C" void kernel_launch(void* const* d_in, const int* in_sizes, int n_in,
                              void* d_out, int out_size)
{
    const float* emb_i = (const float*)d_in[0];
    const float* emb_j = (const float*)d_in[1];
    const int*   tags  = (const int*)d_in[2];
    const int*   docs  = (const int*)d_in[n_in - 1];

    cudaFuncSetAttribute(sim_kernel, cudaFuncAttributeMaxDynamicSharedMemorySize, SIM_DSMEM);

    norm_kernel<<<1024, 128>>>(emb_i, emb_j, (float*)d_out);
    sim_kernel<<<2080, 256, SIM_DSMEM>>>(tags, docs);
    loss_kernel<<<16, 512>>>((float*)d_out);
}